// round 17
// baseline (speedup 1.0000x reference)
#include <cuda_runtime.h>
#include <cuda_fp16.h>

#define C 64
#define MAXN 50000
#define MAXE 800000
#define TPB 256

// Scratch (allocation-free, graph-safe). g_cnt/g_total zero at load and re-zeroed
// by the agg epilogue each invocation. g_bar self-resets; g_gen is monotonic and
// compared against a per-launch base (replay-safe without resets).
__device__ int   g_cnt[MAXN];
__device__ int   g_off[MAXN];
__device__ float g_dis[MAXN];
__device__ int   g_rank[MAXE];
__device__ int   g_srcid[MAXE];
__device__ int   g_total;
__device__ __align__(16) __half2 g_h[MAXN * C / 2];
__device__ unsigned g_bar;
__device__ volatile unsigned g_gen;

__device__ __forceinline__ void grid_barrier(unsigned want, int nb) {
    __syncthreads();
    if (threadIdx.x == 0) {
        __threadfence();
        unsigned a = atomicAdd(&g_bar, 1);
        if (a == (unsigned)(nb - 1)) {
            g_bar = 0;                       // all arrived; none touch g_bar until released
            __threadfence();
            atomicAdd((unsigned*)&g_gen, 1); // release
        } else {
            while (g_gen < want) __nanosleep(64);
        }
        __threadfence();
    }
    __syncthreads();
}

__global__ void __launch_bounds__(TPB) k_fused(
    const float* __restrict__ x, const int* __restrict__ ei,
    const float* __restrict__ W, const float* __restrict__ bias,
    float* __restrict__ out, int N, int E, int nb)
{
    __shared__ __align__(16) float Ws[C * C];   // Ws[k*64+j] = W[j][k]
    __shared__ float As[64][C + 1];
    __shared__ float Ds[64];
    const int* src = ei;
    const int* tgt = ei + E;
    int tid = threadIdx.x;
    int lane = tid & 31;
    int gtid = blockIdx.x * TPB + tid;
    int gstride = nb * TPB;
    unsigned base = g_gen;                      // entry read: before any increment

    // Stage transposed W once (consumed in P3 after two barriers).
    for (int idx = tid; idx < C * C; idx += TPB) {
        int j = idx >> 6, k = idx & 63;
        Ws[k * C + j] = W[idx];
    }

    // ── P1: degree histogram + per-edge rank ──
    for (int i = gtid; i < E; i += gstride)
        g_rank[i] = atomicAdd(&g_cnt[tgt[i]], 1);

    grid_barrier(base + 1, nb);

    // ── P2: CSR offsets (warp scan + global cursor) + deg_inv_sqrt ──
    {
        int Npad = (N + 31) & ~31;
        for (int i = gtid; i < Npad; i += gstride) {
            int c = (i < N) ? g_cnt[i] : 0;
            int v = c;
            #pragma unroll
            for (int d = 1; d < 32; d <<= 1) {
                int u = __shfl_up_sync(0xffffffffu, v, d);
                if (lane >= d) v += u;
            }
            int wtot = __shfl_sync(0xffffffffu, v, 31);
            int wbase = 0;
            if (lane == 31 && wtot) wbase = atomicAdd(&g_total, wtot);
            wbase = __shfl_sync(0xffffffffu, wbase, 31);
            if (i < N) {
                g_off[i] = wbase + v - c;
                g_dis[i] = rsqrtf(fmaxf((float)c, 1.0f));
            }
        }
    }

    grid_barrier(base + 2, nb);

    // ── P3a: CSR fill (no atomics) ──
    for (int i = gtid; i < E; i += gstride)
        g_srcid[g_off[tgt[i]] + g_rank[i]] = src[i];

    // ── P3b: h' = dis * (x @ W^T) in fp16; 64-row tiles, thread = (row, quarter) ──
    {
        int r = tid >> 2, q = tid & 3;
        int ntiles = (N + 63) / 64;
        for (int tile = blockIdx.x; tile < ntiles; tile += nb) {
            int rowbase = tile * 64;
            __syncthreads();                    // protect As/Ds reuse
            for (int idx = tid; idx < 64 * 16; idx += TPB) {
                int rr = idx >> 4, j4 = idx & 15;
                int row = rowbase + rr;
                float4 v = (row < N) ? ((const float4*)(x + (size_t)row * C))[j4]
                                     : make_float4(0.f, 0.f, 0.f, 0.f);
                As[rr][j4 * 4 + 0] = v.x;
                As[rr][j4 * 4 + 1] = v.y;
                As[rr][j4 * 4 + 2] = v.z;
                As[rr][j4 * 4 + 3] = v.w;
            }
            if (tid < 64) {
                int row = rowbase + tid;
                Ds[tid] = (row < N) ? g_dis[row] : 0.0f;
            }
            __syncthreads();

            unsigned long long acc2[8];         // channels 16q .. 16q+15 packed
            #pragma unroll
            for (int p = 0; p < 8; p++) acc2[p] = 0ULL;
            for (int k = 0; k < C; k++) {
                float ak = As[r][k];
                unsigned long long ak2;
                asm("mov.b64 %0, {%1, %1};" : "=l"(ak2) : "f"(ak));
                const ulonglong2* wr = (const ulonglong2*)(Ws + k * C + q * 16);
                #pragma unroll
                for (int qq = 0; qq < 4; qq++) {
                    ulonglong2 w2 = wr[qq];
                    asm("fma.rn.f32x2 %0, %1, %2, %0;" : "+l"(acc2[2 * qq])     : "l"(w2.x), "l"(ak2));
                    asm("fma.rn.f32x2 %0, %1, %2, %0;" : "+l"(acc2[2 * qq + 1]) : "l"(w2.y), "l"(ak2));
                }
            }
            int row = rowbase + r;
            if (row < N) {
                float dis = Ds[r];
                unsigned hw[8];
                #pragma unroll
                for (int p = 0; p < 8; p++) {
                    float e0, e1;
                    asm("mov.b64 {%0, %1}, %2;" : "=f"(e0), "=f"(e1) : "l"(acc2[p]));
                    __half2 hv = __floats2half2_rn(dis * e0, dis * e1);
                    hw[p] = *(unsigned*)&hv;
                }
                uint4* op = (uint4*)(g_h + (size_t)row * (C / 2) + q * 8);
                op[0] = make_uint4(hw[0], hw[1], hw[2], hw[3]);
                op[1] = make_uint4(hw[4], hw[5], hw[6], hw[7]);
            }
        }
    }

    grid_barrier(base + 3, nb);

    // ── P4: aggregate fp16 h' + dis[tgt] + bias + relu -> out; re-zero cnt/total ──
    {
        int gw = (blockIdx.x * (TPB / 32)) + (tid >> 5);
        int nw = nb * (TPB / 32);
        const __half2* hp0 = g_h + lane;
        float2 bb = *(const float2*)(bias + lane * 2);
        for (int w = gw; w < N; w += nw) {
            int off = g_off[w];
            int cnt = g_cnt[w];
            float a0 = 0.0f, a1 = 0.0f;
            int i = 0;
            for (; i + 8 <= cnt; i += 8) {
                int s0 = g_srcid[off + i];
                int s1 = g_srcid[off + i + 1];
                int s2 = g_srcid[off + i + 2];
                int s3 = g_srcid[off + i + 3];
                int s4 = g_srcid[off + i + 4];
                int s5 = g_srcid[off + i + 5];
                int s6 = g_srcid[off + i + 6];
                int s7 = g_srcid[off + i + 7];
                float2 f0 = __half22float2(hp0[(size_t)s0 * (C / 2)]);
                float2 f1 = __half22float2(hp0[(size_t)s1 * (C / 2)]);
                float2 f2 = __half22float2(hp0[(size_t)s2 * (C / 2)]);
                float2 f3 = __half22float2(hp0[(size_t)s3 * (C / 2)]);
                float2 f4 = __half22float2(hp0[(size_t)s4 * (C / 2)]);
                float2 f5 = __half22float2(hp0[(size_t)s5 * (C / 2)]);
                float2 f6 = __half22float2(hp0[(size_t)s6 * (C / 2)]);
                float2 f7 = __half22float2(hp0[(size_t)s7 * (C / 2)]);
                a0 += f0.x + f1.x + f2.x + f3.x + f4.x + f5.x + f6.x + f7.x;
                a1 += f0.y + f1.y + f2.y + f3.y + f4.y + f5.y + f6.y + f7.y;
            }
            for (; i + 2 <= cnt; i += 2) {
                float2 f0 = __half22float2(hp0[(size_t)g_srcid[off + i] * (C / 2)]);
                float2 f1 = __half22float2(hp0[(size_t)g_srcid[off + i + 1] * (C / 2)]);
                a0 += f0.x + f1.x;
                a1 += f0.y + f1.y;
            }
            if (i < cnt) {
                float2 f = __half22float2(hp0[(size_t)g_srcid[off + i] * (C / 2)]);
                a0 += f.x;
                a1 += f.y;
            }
            float dn = g_dis[w];
            float2 r;
            r.x = fmaxf(a0 * dn + bb.x, 0.0f);
            r.y = fmaxf(a1 * dn + bb.y, 0.0f);
            *(float2*)(out + (size_t)w * C + lane * 2) = r;
            if (lane == 0) {
                g_cnt[w] = 0;                 // restore zeros for next invocation
                if (w == 0) g_total = 0;
            }
        }
    }
}

extern "C" void kernel_launch(void* const* d_in, const int* in_sizes, int n_in,
                              void* d_out, int out_size) {
    const float* x   = (const float*)d_in[0];
    const int*   ei  = (const int*)d_in[1];     // int32, [2, E] row-major
    const float* W   = (const float*)d_in[2];
    const float* b   = (const float*)d_in[3];
    float*       out = (float*)d_out;

    int N = in_sizes[0] / C;     // 50000
    int E = in_sizes[1] / 2;     // 800000

    // Grid sized for guaranteed co-residency (software grid barrier).
    int dev = 0;
    cudaGetDevice(&dev);
    int nsm = 148;
    cudaDeviceGetAttribute(&nsm, cudaDevAttrMultiProcessorCount, dev);
    int bpm = 1;
    cudaOccupancyMaxActiveBlocksPerMultiprocessor(&bpm, k_fused, TPB, 0);
    if (bpm < 1) bpm = 1;
    int nb = nsm * bpm;
    if (nb > 2048) nb = 2048;

    k_fused<<<nb, TPB>>>(x, ei, W, b, out, N, E, nb);
}